// round 15
// baseline (speedup 1.0000x reference)
#include <cuda_runtime.h>
#include <cstdint>

#define NQ    32
#define KCB   1024
#define CDIM  8
#define DDIM  1024
#define BDIMS 8
#define TDIM  4096
#define TILE  16
#define NTH   512
#define NCOLS (BDIMS*TDIM)          /* 32768 */
#define BDT   (BDIMS*DDIM*TDIM)     /* 33554432 */
#define NQBT  (NQ*NCOLS)            /* 1048576 */

/* shared memory offsets (floats), total 26416 fl = 105664 B (2 CTAs/SM) */
#define SM_R    0                   /* 1024 d x 4 quads float4 = 16384  */
#define SM_W    16384               /* weights [d][c] : 8192            */
#define SM_ZE   24576               /* 16 t x 9 = 144                   */
#define SM_PART 24736               /* 16 w x 16 ull = 512 fl           */
#define SM_ZQP  25248               /* 16 t x 8 c = 128 fl              */
#define SM_M    25376               /* 16                               */
#define SM_BD   25392               /* 16 w x 32 = 512                  */
#define SM_BK   25904               /* 512                              */
#define SM_TOT  26416
#define SM_BYTES (SM_TOT*4)

typedef unsigned long long ull;

__device__ float g_iwT[NQ * DDIM * CDIM];   /* [q][d][c]                   */
__device__ float g_cbT[NQ * CDIM * KCB];    /* [q][c][k]                   */
__device__ float g_c2 [NQ * KCB];           /* |cb|^2                      */
__device__ float g_Vc [256];                /* [q*8+c] = iw^q[c].obpre^q   */
__device__ float g_obpre[NQ * DDIM];
__device__ float g_obsum[DDIM];

__device__ __forceinline__ ull f2x(float lo, float hi) {
    ull r;
    asm("mov.b64 %0, {%1, %2};" : "=l"(r)
        : "r"(__float_as_uint(lo)), "r"(__float_as_uint(hi)));
    return r;
}
__device__ __forceinline__ void upk(ull v, float& lo, float& hi) {
    unsigned a, b;
    asm("mov.b64 {%0, %1}, %2;" : "=r"(a), "=r"(b) : "l"(v));
    lo = __uint_as_float(a); hi = __uint_as_float(b);
}
#define FMA2(D,A,B,C) asm("fma.rn.f32x2 %0, %1, %2, %3;" : "=l"(D) : "l"(A), "l"(B), "l"(C))
#define ADD2(D,A,B)   asm("add.rn.f32x2 %0, %1, %2;"     : "=l"(D) : "l"(A), "l"(B))

__device__ __forceinline__ unsigned s2u(const void* p) {
    unsigned a;
    asm("{ .reg .u64 t; cvta.to.shared.u64 t, %1; cvt.u32.u64 %0, t; }"
        : "=r"(a) : "l"(p));
    return a;
}
__device__ __forceinline__ void cpa16(unsigned saddr, const void* g) {
    asm volatile("cp.async.cg.shared.global [%0], [%1], 16;" :: "r"(saddr), "l"(g));
}
#define CPA_COMMIT() asm volatile("cp.async.commit_group;")
#define CPA_WAIT0()  asm volatile("cp.async.wait_group 0;")

/* ---------- prep A: ob prefix sums ---------- */
__global__ void prep0_kernel(const float* __restrict__ ob)
{
    int d = blockIdx.x * blockDim.x + threadIdx.x;
    if (d < DDIM) {
        float run = 0.f;
        for (int p = 0; p < NQ; p++) {
            g_obpre[p * DDIM + d] = run;
            run += ob[p * DDIM + d];
        }
        g_obsum[d] = run;
    }
}

/* ---------- prep B: iwT [q][d][c], cbT [q][c][k], |cb|^2 ---------- */
__global__ void prep_kernel(const float* __restrict__ iw,
                            const float* __restrict__ cb)
{
    int idx = blockIdx.x * blockDim.x + threadIdx.x;
    int stride = gridDim.x * blockDim.x;
    for (int i = idx; i < NQ * DDIM * CDIM; i += stride) {
        int q = i >> 13, r = i & 8191, d = r >> 3, c = r & 7;
        g_iwT[i] = iw[(q << 13) + (c << 10) + d];
    }
    for (int i = idx; i < NQ * CDIM * KCB; i += stride) {
        int q = i >> 13, r = i & 8191, c = r >> 10, k = r & 1023;
        g_cbT[i] = cb[(q << 13) + (k << 3) + c];
    }
    for (int k = idx; k < NQ * KCB; k += stride) {
        const float4* row = (const float4*)(cb + (size_t)k * 8);
        float4 a = row[0], b4 = row[1];
        float p = fmaf(a.x, a.x, fmaf(a.y, a.y, fmaf(a.z, a.z, a.w * a.w)));
        float o = fmaf(b4.x, b4.x, fmaf(b4.y, b4.y, fmaf(b4.z, b4.z, b4.w * b4.w)));
        g_c2[k] = p + o;
    }
}

/* ---------- prep C: Vc[q][c] = iw^q[c] . obpre[q] ---------- */
__global__ void prepVc_kernel(const float* __restrict__ iw)
{
    int q = blockIdx.x;
    __shared__ float ps[256];
    int tid = threadIdx.x;
    int c = tid >> 5, slice = tid & 31;
    const float* iwr = iw + (q << 13) + (c << 10) + slice * 32;
    const float* obr = g_obpre + (q << 10) + slice * 32;
    float s = 0.f;
    for (int d = 0; d < 32; d++) s = fmaf(iwr[d], obr[d], s);
    ps[tid] = s;
    __syncthreads();
    if (tid < 8) {
        float t = 0.f;
        #pragma unroll
        for (int j = 0; j < 32; j++) t += ps[tid * 32 + j];
        g_Vc[q * 8 + tid] = t;
    }
}

__global__ __launch_bounds__(NTH, 2)
void rvq_kernel(const float* __restrict__ z,
                const float* __restrict__ ibias,
                const float* __restrict__ ow,
                const float* __restrict__ cb,
                const int*   __restrict__ inlen,
                float* __restrict__ out,
                int wout, int widx, int wlen)
{
    extern __shared__ float sm[];
    float* r_s   = sm + SM_R;
    float* w_s   = sm + SM_W;
    float* ze_s  = sm + SM_ZE;
    ull*   partu = (ull*)(sm + SM_PART);
    float* partf = sm + SM_PART;
    ull*   zqp_u = (ull*)(sm + SM_ZQP);
    float* zqp_f = sm + SM_ZQP;
    float* m_s   = sm + SM_M;
    float* bd_s  = sm + SM_BD;
    int*   bk_s  = (int*)(sm + SM_BK);
    float4* R4   = (float4*)r_s;

    const unsigned sw_u = s2u(w_s);

    const int tid  = threadIdx.x;
    const int lane = tid & 31;
    const int w    = tid >> 5;          /* 0..15 */
    const int tqg  = w >> 2;            /* 0..3 : t-quad (4 t's)   */
    const int dg   = w & 3;             /* 0..3 : 256-d slice      */

    const int col0 = blockIdx.x * TILE;
    const int b    = col0 >> 12;
    const int t0   = col0 & (TDIM - 1);
    const int len  = inlen[b];

    const float* zb = z + (size_t)b * DDIM * TDIM + t0;

    /* 32KB staging: 2048 float4, 4 per thread */
    #define STAGE32(dstu, src) do {                                        \
        const float4* _g = (const float4*)(src);                           \
        cpa16((dstu) + tid * 16,                (const void*)(_g + tid));  \
        cpa16((dstu) + (tid + 512) * 16,  (const void*)(_g + tid + 512));  \
        cpa16((dstu) + (tid + 1024) * 16, (const void*)(_g + tid + 1024)); \
        cpa16((dstu) + (tid + 1536) * 16, (const void*)(_g + tid + 1536)); \
    } while (0)

    if (tid < TILE) m_s[tid] = ((t0 + tid) < len) ? 1.0f : 0.0f;

    /* stage iwT[0] while filling R */
    STAGE32(sw_u, g_iwT);
    CPA_COMMIT();

    /* ---- init residual = z*mask; quads swizzled: slot=d*4+(tq^(d&3)) ---- */
    #pragma unroll
    for (int it = 0; it < 8; it++) {
        int i = tid + it * NTH;          /* 0..4095 */
        int d = i >> 2, tq = i & 3;
        float4 v = *(const float4*)(zb + (size_t)d * TDIM + (tq << 2));
        int tb = t0 + (tq << 2);
        v.x = (tb + 0 < len) ? v.x : 0.0f;
        v.y = (tb + 1 < len) ? v.y : 0.0f;
        v.z = (tb + 2 < len) ? v.z : 0.0f;
        v.w = (tb + 3 < len) ? v.w : 0.0f;
        R4[d * 4 + (tq ^ (d & 3))] = v;
    }

    for (int q = 0; q < NQ; q++) {
        CPA_WAIT0();                     /* iwT[q] staged */
        __syncthreads();

        /* ====== P1: acc[cp*4+tl] += {w2cp,w2cp+1} * {r_tl,r_tl} ====== */
        {
            ull v[16];
            #pragma unroll
            for (int i = 0; i < 16; i++) v[i] = 0ull;

            #pragma unroll 2
            for (int i = 0; i < 8; i++) {
                int d = dg * 256 + (i << 5) + lane;
                ulonglong2 rq = *(const ulonglong2*)&R4[d * 4 + (tqg ^ (d & 3))];
                const ulonglong2* wp = (const ulonglong2*)(w_s + d * 8);
                ulonglong2 W0 = wp[0], W1 = wp[1];
                float a, bb, cc, dd;
                upk(rq.x, a, bb); upk(rq.y, cc, dd);
                ull r0 = f2x(a, a), r1 = f2x(bb, bb);
                ull r2 = f2x(cc, cc), r3 = f2x(dd, dd);
                FMA2(v[0],  W0.x, r0, v[0]);   FMA2(v[1],  W0.x, r1, v[1]);
                FMA2(v[2],  W0.x, r2, v[2]);   FMA2(v[3],  W0.x, r3, v[3]);
                FMA2(v[4],  W0.y, r0, v[4]);   FMA2(v[5],  W0.y, r1, v[5]);
                FMA2(v[6],  W0.y, r2, v[6]);   FMA2(v[7],  W0.y, r3, v[7]);
                FMA2(v[8],  W1.x, r0, v[8]);   FMA2(v[9],  W1.x, r1, v[9]);
                FMA2(v[10], W1.x, r2, v[10]);  FMA2(v[11], W1.x, r3, v[11]);
                FMA2(v[12], W1.y, r0, v[12]);  FMA2(v[13], W1.y, r1, v[13]);
                FMA2(v[14], W1.y, r2, v[14]);  FMA2(v[15], W1.y, r3, v[15]);
            }
            /* split-exchange: 16 ull over 32 lanes */
            int n = 16;
            #pragma unroll
            for (int off = 16; off >= 2; off >>= 1) {
                n >>= 1;
                bool hi = (lane & off) != 0;
                #pragma unroll
                for (int i = 0; i < 8; i++) {
                    if (i < n) {
                        ull send = hi ? v[i] : v[i + n];
                        ull recv = __shfl_xor_sync(0xffffffffu, send, off);
                        ull keep = hi ? v[i + n] : v[i];
                        ADD2(v[i], keep, recv);
                    }
                }
            }
            {
                ull o = __shfl_xor_sync(0xffffffffu, v[0], 1);
                ADD2(v[0], v[0], o);
            }
            if ((lane & 1) == 0)
                partu[w * 16 + ((lane >> 1) & 15)] = v[0];  /* item = cp*4+tl */
        }
        __syncthreads();

        /* ---- stage ow[q] (native [d][c]) into w_s; combine -> ze ---- */
        STAGE32(sw_u, ow + ((size_t)q << 13));
        CPA_COMMIT();
        if (tid < 128) {
            int t = tid >> 3, c = tid & 7;
            int tg_t = t >> 2, tl = t & 3, cp = c >> 1, h = c & 1;
            int item = cp * 4 + tl;
            float s = partf[(((tg_t * 4 + 0) * 16) + item) * 2 + h]
                    + partf[(((tg_t * 4 + 1) * 16) + item) * 2 + h]
                    + partf[(((tg_t * 4 + 2) * 16) + item) * 2 + h]
                    + partf[(((tg_t * 4 + 3) * 16) + item) * 2 + h]
                    + ibias[q * CDIM + c]
                    - m_s[t] * g_Vc[q * 8 + c];
            ze_s[t * 9 + c] = s;
        }
        __syncthreads();

        /* ====== P2: half-warp scans 32 k's from L2; lane = (sub,t) ====== */
        {
            int t = lane & 15, sub = lane >> 4;
            ull ed[8];
            #pragma unroll
            for (int c = 0; c < 8; c++) {
                float e = ze_s[t * 9 + c];
                ed[c] = f2x(e, e);
            }
            const ull n2 = f2x(-2.0f, -2.0f);
            const float* cbt = g_cbT + ((size_t)q << 13);
            const float* c2g = g_c2 + ((size_t)q << 10);
            float best = 3.402823466e38f;
            int bk = 0;
            const int kb = (w << 6) + (sub << 5);
            #pragma unroll 2
            for (int i = 0; i < 8; i++) {
                int k = kb + (i << 2);
                ull sA = 0ull, sB = 0ull;
                #pragma unroll
                for (int c = 0; c < 8; c++) {
                    ulonglong2 cv = *(const ulonglong2*)(cbt + c * 1024 + k);
                    FMA2(sA, cv.x, ed[c], sA);
                    FMA2(sB, cv.y, ed[c], sB);
                }
                ulonglong2 c2v = *(const ulonglong2*)(c2g + k);
                ull bA, bB;
                FMA2(bA, sA, n2, c2v.x);   /* dist = c2 - 2s (e2 rank-invariant) */
                FMA2(bB, sB, n2, c2v.y);
                float da, db, dc, dd;
                upk(bA, da, db); upk(bB, dc, dd);
                if (da < best) { best = da; bk = k;     }
                if (db < best) { best = db; bk = k + 1; }
                if (dc < best) { best = dc; bk = k + 2; }
                if (dd < best) { best = dd; bk = k + 3; }
            }
            bd_s[w * 32 + lane] = best;
            bk_s[w * 32 + lane] = bk;
        }
        __syncthreads();

        /* ---- final argmin over 32 chunks (k-ascending) + select ---- */
        if (tid < TILE) {
            int t = tid;
            float best = 3.402823466e38f;
            int bk = 0;
            #pragma unroll
            for (int ch = 0; ch < 32; ch++) {       /* (w2,sub) lex = k asc */
                int idx = (ch >> 1) * 32 + (ch & 1) * 16 + t;
                float d2 = bd_s[idx];
                if (d2 < best) { best = d2; bk = bk_s[idx]; }
            }
            if (widx) out[BDT + q * NCOLS + col0 + t] = (float)bk;
            float mt = m_s[t];
            const float4* cr = (const float4*)(cb + (((size_t)q << 10) + bk) * 8);
            float4 ca = cr[0], cb4 = cr[1];
            float* zp = zqp_f + t * 8;              /* natural c order */
            zp[0] = -ca.x * mt;  zp[1] = -ca.y * mt;
            zp[2] = -ca.z * mt;  zp[3] = -ca.w * mt;
            zp[4] = -cb4.x * mt; zp[5] = -cb4.y * mt;
            zp[6] = -cb4.z * mt; zp[7] = -cb4.w * mt;
        }
        CPA_WAIT0();                    /* ow[q] staged */
        __syncthreads();

        /* ====== P3: r_t += sum_cp {w2cp,w2cp+1}.{-zq2cp,-zq2cp+1} ====== */
        {
            ull zq[16];                 /* [tl*4+cp] pair {c=2cp, c=2cp+1} */
            {
                const ulonglong2* zp = (const ulonglong2*)(zqp_u + tqg * 16);
                #pragma unroll
                for (int j = 0; j < 8; j++) {
                    ulonglong2 p = zp[j];
                    zq[j * 2] = p.x; zq[j * 2 + 1] = p.y;
                }
            }
            #pragma unroll 2
            for (int i = 0; i < 8; i++) {
                int d = dg * 256 + (i << 5) + lane;
                int slot = d * 4 + (tqg ^ (d & 3));
                float4 r = R4[slot];
                const ulonglong2* wp = (const ulonglong2*)(w_s + d * 8);
                ulonglong2 W0 = wp[0], W1 = wp[1];
                float* rp = (float*)&r;
                #pragma unroll
                for (int tl = 0; tl < 4; tl++) {
                    ull acc = 0ull;
                    FMA2(acc, W0.x, zq[tl * 4 + 0], acc);
                    FMA2(acc, W0.y, zq[tl * 4 + 1], acc);
                    FMA2(acc, W1.x, zq[tl * 4 + 2], acc);
                    FMA2(acc, W1.y, zq[tl * 4 + 3], acc);
                    float a, bb; upk(acc, a, bb);
                    rp[tl] = rp[tl] + a + bb;       /* zq pre-negated */
                }
                R4[slot] = r;
            }
        }
        __syncthreads();

        /* ---- stage iwT[q+1] (w_s free post-barrier) ---- */
        if (q + 1 < NQ) {
            STAGE32(sw_u, g_iwT + ((size_t)(q + 1) << 13));
            CPA_COMMIT();
        }
    }

    /* ---- epilogue: qout = z*m - r_noob + obsum*m ---- */
    if (wout) {
        #pragma unroll
        for (int it = 0; it < 8; it++) {
            int i = tid + it * NTH;
            int d = i >> 2, tq = i & 3;
            float4 zv = *(const float4*)(zb + (size_t)d * TDIM + (tq << 2));
            float4 rv = R4[d * 4 + (tq ^ (d & 3))];
            float obv = g_obsum[d];
            int tb = t0 + (tq << 2);
            float4 o;
            o.x = ((tb + 0 < len) ? zv.x + obv : 0.0f) - rv.x;
            o.y = ((tb + 1 < len) ? zv.y + obv : 0.0f) - rv.y;
            o.z = ((tb + 2 < len) ? zv.z + obv : 0.0f) - rv.z;
            o.w = ((tb + 3 < len) ? zv.w + obv : 0.0f) - rv.w;
            *(float4*)(out + (size_t)b * DDIM * TDIM + (size_t)d * TDIM + t0 + (tq << 2)) = o;
        }
    }
    if (wlen && blockIdx.x == 0 && tid < BDIMS)
        out[BDT + NQBT + tid] = (float)inlen[tid];
}

extern "C" void kernel_launch(void* const* d_in, const int* in_sizes, int n_in,
                              void* d_out, int out_size)
{
    const float* z   = (const float*)d_in[0];
    const float* iw  = (const float*)d_in[1];
    const float* ib  = (const float*)d_in[2];
    const float* ow  = (const float*)d_in[3];
    const float* ob  = (const float*)d_in[4];
    const float* cbk = (const float*)d_in[5];
    const int* inlen = (const int*)d_in[6];
    float* out = (float*)d_out;

    cudaFuncSetAttribute(rvq_kernel, cudaFuncAttributeMaxDynamicSharedMemorySize, SM_BYTES);

    int wout = (out_size >= BDT) ? 1 : 0;
    int widx = (out_size >= BDT + NQBT) ? 1 : 0;
    int wlen = (out_size >= BDT + NQBT + BDIMS) ? 1 : 0;

    prep0_kernel<<<4, 256>>>(ob);
    prep_kernel<<<256, 512>>>(iw, cbk);
    prepVc_kernel<<<NQ, 256>>>(iw);
    rvq_kernel<<<NCOLS / TILE, NTH, SM_BYTES>>>(z, ib, ow, cbk, inlen,
                                               out, wout, widx, wlen);
}

// round 16
// speedup vs baseline: 1.4995x; 1.4995x over previous
#include <cuda_runtime.h>
#include <cstdint>

#define NQ    32
#define KCB   1024
#define CDIM  8
#define DDIM  1024
#define BDIMS 8
#define TDIM  4096
#define TILE  32
#define NTH   1024
#define NCOLS (BDIMS*TDIM)          /* 32768 */
#define BDT   (BDIMS*DDIM*TDIM)     /* 33554432 */
#define NQBT  (NQ*NCOLS)            /* 1048576 */

/* shared memory offsets (floats), total 53824 fl = 215296 B */
#define SM_R    0                   /* 1024 x 32 residual, swizzled float4  */
#define SM_W    32768               /* 8 x 1024 : iw (P1) then owT (P3)     */
#define SM_CBT  40960               /* cbT: 8 x 1024                        */
#define SM_C2   49152               /* 1024                                 */
#define SM_ZE   50176               /* 32 x 9 = 288                         */
#define SM_PART 50464               /* 32 w x 16 ull = 1024 fl              */
#define SM_ZQP  51488               /* 16 pairs x 8 c x ull = 256 fl        */
#define SM_M    51744               /* 32                                   */
#define SM_BD   51776               /* 32 w x 32 = 1024                     */
#define SM_BK   52800               /* 1024                                 */
#define SM_TOT  53824
#define SM_BYTES (SM_TOT*4)

typedef unsigned long long ull;

__device__ float g_owT[NQ * CDIM * DDIM];   /* [q][c][d] */
__device__ float g_cbT[NQ * CDIM * KCB];    /* [q][c][k] */
__device__ float g_c2 [NQ * KCB];           /* |cb|^2    */
__device__ float g_Vc [256];                /* [q*8+c] = iw^q[c] . obpre^q */
__device__ float g_obpre[NQ * DDIM];        /* prefix sum of ob (p < q)    */
__device__ float g_obsum[DDIM];             /* total sum of ob             */

__device__ __forceinline__ ull f2x(float lo, float hi) {
    ull r;
    asm("mov.b64 %0, {%1, %2};" : "=l"(r)
        : "r"(__float_as_uint(lo)), "r"(__float_as_uint(hi)));
    return r;
}
__device__ __forceinline__ void upk(ull v, float& lo, float& hi) {
    unsigned a, b;
    asm("mov.b64 {%0, %1}, %2;" : "=r"(a), "=r"(b) : "l"(v));
    lo = __uint_as_float(a); hi = __uint_as_float(b);
}
#define FMA2(D,A,B,C) asm("fma.rn.f32x2 %0, %1, %2, %3;" : "=l"(D) : "l"(A), "l"(B), "l"(C))
#define ADD2(D,A,B)   asm("add.rn.f32x2 %0, %1, %2;"     : "=l"(D) : "l"(A), "l"(B))

__device__ __forceinline__ unsigned s2u(const void* p) {
    unsigned a;
    asm("{ .reg .u64 t; cvta.to.shared.u64 t, %1; cvt.u32.u64 %0, t; }"
        : "=r"(a) : "l"(p));
    return a;
}
__device__ __forceinline__ void cpa16(unsigned saddr, const void* g) {
    asm volatile("cp.async.cg.shared.global [%0], [%1], 16;" :: "r"(saddr), "l"(g));
}
#define CPA_COMMIT() asm volatile("cp.async.commit_group;")
#define CPA_WAIT0()  asm volatile("cp.async.wait_group 0;")
#define CPA_WAIT1()  asm volatile("cp.async.wait_group 1;")

/* ---------- prep A: ob prefix sums ---------- */
__global__ void prep0_kernel(const float* __restrict__ ob)
{
    int d = blockIdx.x * blockDim.x + threadIdx.x;
    if (d < DDIM) {
        float run = 0.f;
        for (int p = 0; p < NQ; p++) {
            g_obpre[p * DDIM + d] = run;
            run += ob[p * DDIM + d];
        }
        g_obsum[d] = run;
    }
}

/* ---------- prep B: transposes + |cb|^2 ---------- */
__global__ void prep_kernel(const float* __restrict__ ow,
                            const float* __restrict__ cb)
{
    int idx = blockIdx.x * blockDim.x + threadIdx.x;
    int stride = gridDim.x * blockDim.x;
    for (int i = idx; i < NQ * CDIM * DDIM; i += stride) {
        int q = i >> 13, r = i & 8191, c = r >> 10, d = r & 1023;
        g_owT[i] = ow[(q << 13) + (d << 3) + c];
    }
    for (int i = idx; i < NQ * CDIM * KCB; i += stride) {
        int q = i >> 13, r = i & 8191, c = r >> 10, k = r & 1023;
        g_cbT[i] = cb[(q << 13) + (k << 3) + c];
    }
    for (int k = idx; k < NQ * KCB; k += stride) {
        const float4* row = (const float4*)(cb + (size_t)k * 8);
        float4 a = row[0], b4 = row[1];
        float p = fmaf(a.x, a.x, fmaf(a.y, a.y, fmaf(a.z, a.z, a.w * a.w)));
        float o = fmaf(b4.x, b4.x, fmaf(b4.y, b4.y, fmaf(b4.z, b4.z, b4.w * b4.w)));
        g_c2[k] = p + o;
    }
}

/* ---------- prep C: Vc[q][c] = iw^q[c] . obpre[q] ---------- */
__global__ void prepVc_kernel(const float* __restrict__ iw)
{
    int q = blockIdx.x;
    __shared__ float ps[256];
    int tid = threadIdx.x;
    int c = tid >> 5, slice = tid & 31;
    const float* iwr = iw + (q << 13) + (c << 10) + slice * 32;
    const float* obr = g_obpre + (q << 10) + slice * 32;
    float s = 0.f;
    for (int d = 0; d < 32; d++) s = fmaf(iwr[d], obr[d], s);
    ps[tid] = s;
    __syncthreads();
    if (tid < 8) {
        float t = 0.f;
        #pragma unroll
        for (int j = 0; j < 32; j++) t += ps[tid * 32 + j];
        g_Vc[q * 8 + tid] = t;
    }
}

__global__ __launch_bounds__(NTH, 1)
void rvq_kernel(const float* __restrict__ z,
                const float* __restrict__ iw,
                const float* __restrict__ ibias,
                const float* __restrict__ cb,
                const int*   __restrict__ inlen,
                float* __restrict__ out,
                int wout, int widx, int wlen)
{
    extern __shared__ float sm[];
    float* r_s   = sm + SM_R;
    float* w_s   = sm + SM_W;
    float* cbt_s = sm + SM_CBT;
    float* c2_s  = sm + SM_C2;
    float* ze_s  = sm + SM_ZE;
    ull*   partu = (ull*)(sm + SM_PART);
    float* partf = sm + SM_PART;
    ull*   zqp_u = (ull*)(sm + SM_ZQP);
    float* zqp_f = sm + SM_ZQP;
    float* m_s   = sm + SM_M;
    float* bd_s  = sm + SM_BD;
    int*   bk_s  = (int*)(sm + SM_BK);
    float4* R4   = (float4*)r_s;

    const unsigned sw_u   = s2u(w_s);
    const unsigned scbt_u = s2u(cbt_s);
    const unsigned sc2_u  = s2u(c2_s);

    const int tid  = threadIdx.x;
    const int lane = tid & 31;
    const int w    = tid >> 5;          /* 0..31 */
    /* P1 & P3: 8 t-quad-groups x 4 d-slices */
    const int tqg  = w >> 2;            /* 0..7 : t-quad (4 t's)  */
    const int dg   = w & 3;             /* 0..3 : 256-d slice     */

    const int col0 = blockIdx.x * TILE;
    const int b    = col0 >> 12;
    const int t0   = col0 & (TDIM - 1);
    const int len  = inlen[b];

    const float* zb = z + (size_t)b * DDIM * TDIM + t0;

    /* staging: 32KB arrays = 2048 float4 -> 2 per thread; 4KB -> tid<256 */
    #define STAGE32(dstu, src) do {                                        \
        const float4* _g = (const float4*)(src);                           \
        cpa16((dstu) + tid * 16,               (const void*)(_g + tid));   \
        cpa16((dstu) + (tid + 1024) * 16, (const void*)(_g + tid + 1024)); \
    } while (0)
    #define STAGE4(dstu, src) do {                                         \
        if (tid < 256) {                                                   \
            const float4* _g = (const float4*)(src);                       \
            cpa16((dstu) + tid * 16, (const void*)(_g + tid));             \
        }                                                                  \
    } while (0)

    if (tid < TILE) m_s[tid] = ((t0 + tid) < len) ? 1.0f : 0.0f;

    /* kick q=0 staging while we fill R */
    STAGE32(sw_u,   iw);
    STAGE32(scbt_u, g_cbT);
    STAGE4(sc2_u,   g_c2);
    CPA_COMMIT();

    /* ---- init residual(no-ob form) = z * mask ---- */
    #pragma unroll
    for (int it = 0; it < 8; it++) {
        int i = tid + it * NTH;
        int d = i >> 3, tq = i & 7;
        float4 v = *(const float4*)(zb + (size_t)d * TDIM + (tq << 2));
        int tb = t0 + (tq << 2);
        v.x = (tb + 0 < len) ? v.x : 0.0f;
        v.y = (tb + 1 < len) ? v.y : 0.0f;
        v.z = (tb + 2 < len) ? v.z : 0.0f;
        v.w = (tb + 3 < len) ? v.w : 0.0f;
        R4[d * 8 + (tq ^ (d & 7))] = v;
    }

    for (int q = 0; q < NQ; q++) {
        CPA_WAIT0();
        __syncthreads();

        /* ====== P1 (8tqg x 4dg): 4 t x 256 d per warp; v[p*8+c] ====== */
        {
            ull v[16];
            #pragma unroll
            for (int i = 0; i < 16; i++) v[i] = 0ull;

            #pragma unroll 2
            for (int i = 0; i < 8; i++) {
                int d = dg * 256 + (i << 5) + lane;
                ulonglong2 rq = *(const ulonglong2*)&R4[d * 8 + (tqg ^ (d & 7))];
                #pragma unroll
                for (int c = 0; c < 8; c++) {
                    float wv = w_s[c * 1024 + d];
                    ull wd = f2x(wv, wv);
                    FMA2(v[c],     wd, rq.x, v[c]);       /* pair 0: t0,t1 */
                    FMA2(v[8 + c], wd, rq.y, v[8 + c]);   /* pair 1: t2,t3 */
                }
            }
            /* split-exchange: 16 ull over 32 lanes (R8-proven) */
            int n = 16;
            #pragma unroll
            for (int off = 16; off >= 2; off >>= 1) {
                n >>= 1;
                bool hi = (lane & off) != 0;
                #pragma unroll
                for (int i = 0; i < 8; i++) {
                    if (i < n) {
                        ull send = hi ? v[i] : v[i + n];
                        ull recv = __shfl_xor_sync(0xffffffffu, send, off);
                        ull keep = hi ? v[i + n] : v[i];
                        ADD2(v[i], keep, recv);
                    }
                }
            }
            {
                ull o = __shfl_xor_sync(0xffffffffu, v[0], 1);
                ADD2(v[0], v[0], o);
            }
            if ((lane & 1) == 0) {
                int idx = ((lane & 16) >> 1) | ((lane >> 1) & 7);  /* p*8+c */
                partu[w * 16 + idx] = v[0];
            }
        }
        __syncthreads();

        /* ---- issue ow[q] (w_s free); combine partials -> ze ---- */
        STAGE32(sw_u, g_owT + ((size_t)q << 13));
        CPA_COMMIT();
        if (tid < 256) {
            int t = tid >> 3, c = tid & 7;
            int tg_t = t >> 2, p = (t & 3) >> 1, h = t & 1;
            int item = p * 8 + c;
            float s = partf[((tg_t * 4 + 0) * 16 + item) * 2 + h]
                    + partf[((tg_t * 4 + 1) * 16 + item) * 2 + h]
                    + partf[((tg_t * 4 + 2) * 16 + item) * 2 + h]
                    + partf[((tg_t * 4 + 3) * 16 + item) * 2 + h]
                    + ibias[q * CDIM + c]
                    - m_s[t] * g_Vc[q * 8 + c];
            ze_s[t * 9 + c] = s;
        }
        __syncthreads();

        /* ====== P2: lane = t, warp = 32 k's (packed k-quads) ====== */
        {
            int t = lane;
            ull ed[8];
            #pragma unroll
            for (int c = 0; c < 8; c++) {
                float e = ze_s[t * 9 + c];
                ed[c] = f2x(e, e);
            }
            const ull n2 = f2x(-2.0f, -2.0f);
            float best = 3.402823466e38f;
            int bk = 0;
            const int kb = w << 5;
            #pragma unroll 4
            for (int i = 0; i < 8; i++) {
                int k = kb + (i << 2);
                ull sA = 0ull, sB = 0ull;
                #pragma unroll
                for (int c = 0; c < 8; c++) {
                    ulonglong2 cv = *(const ulonglong2*)(cbt_s + c * 1024 + k);
                    FMA2(sA, cv.x, ed[c], sA);
                    FMA2(sB, cv.y, ed[c], sB);
                }
                ulonglong2 c2v = *(const ulonglong2*)(c2_s + k);
                ull bA, bB;
                FMA2(bA, sA, n2, c2v.x);   /* dist = c2 - 2s (e2 rank-invariant) */
                FMA2(bB, sB, n2, c2v.y);
                float da, db, dc, dd;
                upk(bA, da, db); upk(bB, dc, dd);
                if (da < best) { best = da; bk = k;     }
                if (db < best) { best = db; bk = k + 1; }
                if (dc < best) { best = dc; bk = k + 2; }
                if (dd < best) { best = dd; bk = k + 3; }
            }
            bd_s[w * 32 + t] = best;
            bk_s[w * 32 + t] = bk;
        }
        __syncthreads();

        /* ---- prefetch cbT/c2[q+1]; select; wait ow ---- */
        if (q + 1 < NQ) {
            STAGE32(scbt_u, g_cbT + ((size_t)(q + 1) << 13));
            STAGE4(sc2_u,   g_c2 + ((size_t)(q + 1) << 10));
        }
        CPA_COMMIT();
        if (tid < TILE) {
            int t = tid;
            float best = bd_s[t];
            int bk = bk_s[t];
            #pragma unroll
            for (int kc = 1; kc < 32; kc++) {   /* warp order = k ascending */
                float d2 = bd_s[kc * 32 + t];
                if (d2 < best) { best = d2; bk = bk_s[kc * 32 + t]; }
            }
            if (widx) out[BDT + q * NCOLS + col0 + t] = (float)bk;
            float mt = m_s[t];
            const float4* cr = (const float4*)(cb + (((size_t)q << 10) + bk) * 8);
            float4 ca = cr[0], cb4 = cr[1];
            /* pair = t>>1, half = t&1 ; zqp_u[pair*8+c] */
            float* zp = zqp_f + (t >> 1) * 16 + (t & 1);
            zp[0]  = -ca.x * mt;  zp[2]  = -ca.y * mt;
            zp[4]  = -ca.z * mt;  zp[6]  = -ca.w * mt;
            zp[8]  = -cb4.x * mt; zp[10] = -cb4.y * mt;
            zp[12] = -cb4.z * mt; zp[14] = -cb4.w * mt;
        }
        CPA_WAIT1();            /* ow[q] done; cbT[q+1] may stay in flight */
        __syncthreads();

        /* ====== P3 (8tqg x 4dg): r -= ow.zq  (no ob) ====== */
        {
            ull zqA[8], zqB[8];
            #pragma unroll
            for (int c = 0; c < 8; c++) {
                zqA[c] = zqp_u[(tqg * 2 + 0) * 8 + c];
                zqB[c] = zqp_u[(tqg * 2 + 1) * 8 + c];
            }
            #pragma unroll 2
            for (int i = 0; i < 8; i++) {
                int d = dg * 256 + (i << 5) + lane;
                int slot = d * 8 + (tqg ^ (d & 7));
                ulonglong2 r = *(const ulonglong2*)&R4[slot];
                #pragma unroll
                for (int c = 0; c < 8; c++) {
                    float wv = w_s[c * 1024 + d];
                    ull wd = f2x(wv, wv);
                    FMA2(r.x, wd, zqA[c], r.x);
                    FMA2(r.y, wd, zqB[c], r.y);
                }
                *(ulonglong2*)&R4[slot] = r;
            }
        }
        __syncthreads();

        /* ---- issue iw[q+1] (w_s free post-barrier) ---- */
        if (q + 1 < NQ) {
            STAGE32(sw_u, iw + ((size_t)(q + 1) << 13));
        }
        CPA_COMMIT();
    }

    /* ---- epilogue: qout = z*m - r_noob + obsum*m ---- */
    if (wout) {
        #pragma unroll
        for (int it = 0; it < 8; it++) {
            int i = tid + it * NTH;
            int d = i >> 3, tq = i & 7;
            float4 zv = *(const float4*)(zb + (size_t)d * TDIM + (tq << 2));
            float4 rv = R4[d * 8 + (tq ^ (d & 7))];
            float obv = g_obsum[d];
            int tb = t0 + (tq << 2);
            float4 o;
            o.x = ((tb + 0 < len) ? zv.x + obv : 0.0f) - rv.x;
            o.y = ((tb + 1 < len) ? zv.y + obv : 0.0f) - rv.y;
            o.z = ((tb + 2 < len) ? zv.z + obv : 0.0f) - rv.z;
            o.w = ((tb + 3 < len) ? zv.w + obv : 0.0f) - rv.w;
            *(float4*)(out + (size_t)b * DDIM * TDIM + (size_t)d * TDIM + t0 + (tq << 2)) = o;
        }
    }
    if (wlen && blockIdx.x == 0 && tid < BDIMS)
        out[BDT + NQBT + tid] = (float)inlen[tid];
}

extern "C" void kernel_launch(void* const* d_in, const int* in_sizes, int n_in,
                              void* d_out, int out_size)
{
    const float* z   = (const float*)d_in[0];
    const float* iw  = (const float*)d_in[1];
    const float* ib  = (const float*)d_in[2];
    const float* ow  = (const float*)d_in[3];
    const float* ob  = (const float*)d_in[4];
    const float* cbk = (const float*)d_in[5];
    const int* inlen = (const int*)d_in[6];
    float* out = (float*)d_out;

    cudaFuncSetAttribute(rvq_kernel, cudaFuncAttributeMaxDynamicSharedMemorySize, SM_BYTES);

    int wout = (out_size >= BDT) ? 1 : 0;
    int widx = (out_size >= BDT + NQBT) ? 1 : 0;
    int wlen = (out_size >= BDT + NQBT + BDIMS) ? 1 : 0;

    prep0_kernel<<<4, 256>>>(ob);
    prep_kernel<<<256, 512>>>(ow, cbk);
    prepVc_kernel<<<NQ, 256>>>(iw);
    rvq_kernel<<<NCOLS / TILE, NTH, SM_BYTES>>>(z, iw, ib, cbk, inlen,
                                               out, wout, widx, wlen);
}

// round 17
// speedup vs baseline: 1.7074x; 1.1387x over previous
#include <cuda_runtime.h>
#include <cstdint>

#define NQ    32
#define KCB   1024
#define CDIM  8
#define DDIM  1024
#define BDIMS 8
#define TDIM  4096
#define TILE  32
#define NTH   512
#define NCOLS (BDIMS*TDIM)          /* 32768 */
#define BDT   (BDIMS*DDIM*TDIM)     /* 33554432 */
#define NQBT  (NQ*NCOLS)            /* 1048576 */

/* shared memory offsets (floats) */
#define SM_R    0                   /* 1024 x 32 residual, swizzled float4  */
#define SM_W    32768               /* 8 x 1024 : iw (P1) then owT (P3)     */
#define SM_CBT  40960               /* cbT: 8 x 1024                        */
#define SM_C2   49152               /* 1024                                 */
#define SM_ZE   50176               /* 32 x 9 = 288                         */
#define SM_PART 50464               /* 16 w x 32 ull = 1024 fl              */
#define SM_ZQP  51488               /* 16 pairs x 8 c x ull = 256 fl        */
#define SM_M    51744               /* 32                                   */
#define SM_BD   51776               /* 512                                  */
#define SM_BK   52288               /* 512                                  */
#define SM_IB   52800               /* 256: all ibias                       */
#define SM_VC   53056               /* 256: all Vc                          */
#define SM_TOT  53312
#define SM_BYTES (SM_TOT*4)

typedef unsigned long long ull;

__device__ float g_owT[NQ * CDIM * DDIM];   /* [q][c][d] */
__device__ float g_cbT[NQ * CDIM * KCB];    /* [q][c][k] */
__device__ float g_c2 [NQ * KCB];           /* |cb|^2    */
__device__ float g_Vc [256];                /* [q*8+c] = iw^q[c] . obpre^q */
__device__ float g_obpre[NQ * DDIM];        /* prefix sum of ob (p < q)    */
__device__ float g_obsum[DDIM];             /* total sum of ob             */

__device__ __forceinline__ ull f2x(float lo, float hi) {
    ull r;
    asm("mov.b64 %0, {%1, %2};" : "=l"(r)
        : "r"(__float_as_uint(lo)), "r"(__float_as_uint(hi)));
    return r;
}
__device__ __forceinline__ void upk(ull v, float& lo, float& hi) {
    unsigned a, b;
    asm("mov.b64 {%0, %1}, %2;" : "=r"(a), "=r"(b) : "l"(v));
    lo = __uint_as_float(a); hi = __uint_as_float(b);
}
#define FMA2(D,A,B,C) asm("fma.rn.f32x2 %0, %1, %2, %3;" : "=l"(D) : "l"(A), "l"(B), "l"(C))
#define ADD2(D,A,B)   asm("add.rn.f32x2 %0, %1, %2;"     : "=l"(D) : "l"(A), "l"(B))

__device__ __forceinline__ unsigned s2u(const void* p) {
    unsigned a;
    asm("{ .reg .u64 t; cvta.to.shared.u64 t, %1; cvt.u32.u64 %0, t; }"
        : "=r"(a) : "l"(p));
    return a;
}
__device__ __forceinline__ void cpa16(unsigned saddr, const void* g) {
    asm volatile("cp.async.cg.shared.global [%0], [%1], 16;" :: "r"(saddr), "l"(g));
}
#define CPA_COMMIT() asm volatile("cp.async.commit_group;")
#define CPA_WAIT0()  asm volatile("cp.async.wait_group 0;")
#define CPA_WAIT1()  asm volatile("cp.async.wait_group 1;")

/* ---------- prep A: ob prefix sums ---------- */
__global__ void prep0_kernel(const float* __restrict__ ob)
{
    int d = blockIdx.x * blockDim.x + threadIdx.x;
    if (d < DDIM) {
        float run = 0.f;
        for (int p = 0; p < NQ; p++) {
            g_obpre[p * DDIM + d] = run;
            run += ob[p * DDIM + d];
        }
        g_obsum[d] = run;
    }
}

/* ---------- prep B: transposes + |cb|^2 ---------- */
__global__ void prep_kernel(const float* __restrict__ ow,
                            const float* __restrict__ cb)
{
    int idx = blockIdx.x * blockDim.x + threadIdx.x;
    int stride = gridDim.x * blockDim.x;
    for (int i = idx; i < NQ * CDIM * DDIM; i += stride) {
        int q = i >> 13, r = i & 8191, c = r >> 10, d = r & 1023;
        g_owT[i] = ow[(q << 13) + (d << 3) + c];
    }
    for (int i = idx; i < NQ * CDIM * KCB; i += stride) {
        int q = i >> 13, r = i & 8191, c = r >> 10, k = r & 1023;
        g_cbT[i] = cb[(q << 13) + (k << 3) + c];
    }
    for (int k = idx; k < NQ * KCB; k += stride) {
        const float4* row = (const float4*)(cb + (size_t)k * 8);
        float4 a = row[0], b4 = row[1];
        float p = fmaf(a.x, a.x, fmaf(a.y, a.y, fmaf(a.z, a.z, a.w * a.w)));
        float o = fmaf(b4.x, b4.x, fmaf(b4.y, b4.y, fmaf(b4.z, b4.z, b4.w * b4.w)));
        g_c2[k] = p + o;
    }
}

/* ---------- prep C: Vc[q][c] = iw^q[c] . obpre[q] ---------- */
__global__ void prepVc_kernel(const float* __restrict__ iw)
{
    int q = blockIdx.x;
    __shared__ float ps[256];
    int tid = threadIdx.x;
    int c = tid >> 5, slice = tid & 31;
    const float* iwr = iw + (q << 13) + (c << 10) + slice * 32;
    const float* obr = g_obpre + (q << 10) + slice * 32;
    float s = 0.f;
    for (int d = 0; d < 32; d++) s = fmaf(iwr[d], obr[d], s);
    ps[tid] = s;
    __syncthreads();
    if (tid < 8) {
        float t = 0.f;
        #pragma unroll
        for (int j = 0; j < 32; j++) t += ps[tid * 32 + j];
        g_Vc[q * 8 + tid] = t;
    }
}

__global__ __launch_bounds__(NTH, 1)
void rvq_kernel(const float* __restrict__ z,
                const float* __restrict__ iw,
                const float* __restrict__ ibias,
                const float* __restrict__ cb,
                const int*   __restrict__ inlen,
                float* __restrict__ out,
                int wout, int widx, int wlen)
{
    extern __shared__ float sm[];
    float* r_s   = sm + SM_R;
    float* w_s   = sm + SM_W;
    float* cbt_s = sm + SM_CBT;
    float* c2_s  = sm + SM_C2;
    float* ze_s  = sm + SM_ZE;
    ull*   partu = (ull*)(sm + SM_PART);
    float* partf = sm + SM_PART;
    ull*   zqp_u = (ull*)(sm + SM_ZQP);
    float* zqp_f = sm + SM_ZQP;
    float* m_s   = sm + SM_M;
    float* bd_s  = sm + SM_BD;
    int*   bk_s  = (int*)(sm + SM_BK);
    float* ib_s  = sm + SM_IB;
    float* vc_s  = sm + SM_VC;
    float4* R4   = (float4*)r_s;

    const unsigned sw_u   = s2u(w_s);
    const unsigned scbt_u = s2u(cbt_s);
    const unsigned sc2_u  = s2u(c2_s);

    const int tid  = threadIdx.x;
    const int lane = tid & 31;
    const int w    = tid >> 5;          /* 0..15 */
    const int tg   = w >> 2;            /* 0..3 : 8-t group   */
    const int dg   = w & 3;             /* 0..3 : 256-d slice */
    const int tqa  = tg << 1, tqb = tqa + 1;

    const int col0 = blockIdx.x * TILE;
    const int b    = col0 >> 12;
    const int t0   = col0 & (TDIM - 1);
    const int len  = inlen[b];

    const float* zb = z + (size_t)b * DDIM * TDIM + t0;

    #define STAGE32(dstu, src) do {                                        \
        const float4* _g = (const float4*)(src);                           \
        cpa16((dstu) + tid * 16,                (const void*)(_g + tid));  \
        cpa16((dstu) + (tid + 512) * 16,  (const void*)(_g + tid + 512));  \
        cpa16((dstu) + (tid + 1024) * 16, (const void*)(_g + tid + 1024)); \
        cpa16((dstu) + (tid + 1536) * 16, (const void*)(_g + tid + 1536)); \
    } while (0)
    #define STAGE4(dstu, src) do {                                         \
        if (tid < 256) {                                                   \
            const float4* _g = (const float4*)(src);                       \
            cpa16((dstu) + tid * 16, (const void*)(_g + tid));             \
        }                                                                  \
    } while (0)

    if (tid < TILE) m_s[tid] = ((t0 + tid) < len) ? 1.0f : 0.0f;
    if (tid < 256) {                     /* hoist ibias + Vc into smem */
        ib_s[tid] = ibias[tid];
        vc_s[tid] = g_Vc[tid];
    }

    STAGE32(sw_u,   iw);
    STAGE32(scbt_u, g_cbT);
    STAGE4(sc2_u,   g_c2);
    CPA_COMMIT();

    #pragma unroll
    for (int it = 0; it < 16; it++) {
        int i = tid + it * NTH;
        int d = i >> 3, tq = i & 7;
        float4 v = *(const float4*)(zb + (size_t)d * TDIM + (tq << 2));
        int tb = t0 + (tq << 2);
        v.x = (tb + 0 < len) ? v.x : 0.0f;
        v.y = (tb + 1 < len) ? v.y : 0.0f;
        v.z = (tb + 2 < len) ? v.z : 0.0f;
        v.w = (tb + 3 < len) ? v.w : 0.0f;
        R4[d * 8 + (tq ^ (d & 7))] = v;
    }

    for (int q = 0; q < NQ; q++) {
        CPA_WAIT0();
        __syncthreads();

        /* ====== phase 1 (packed, 4tg x 4dg) ====== */
        {
            ull v[32];
            #pragma unroll
            for (int i = 0; i < 32; i++) v[i] = 0ull;

            #pragma unroll 2
            for (int i = 0; i < 8; i++) {
                int d = dg * 256 + (i << 5) + lane;
                ulonglong2 rA = *(const ulonglong2*)&R4[d * 8 + (tqa ^ (d & 7))];
                ulonglong2 rB = *(const ulonglong2*)&R4[d * 8 + (tqb ^ (d & 7))];
                #pragma unroll
                for (int c = 0; c < 8; c++) {
                    float wv = w_s[c * 1024 + d];
                    ull wd = f2x(wv, wv);
                    FMA2(v[c * 4 + 0], wd, rA.x, v[c * 4 + 0]);
                    FMA2(v[c * 4 + 1], wd, rA.y, v[c * 4 + 1]);
                    FMA2(v[c * 4 + 2], wd, rB.x, v[c * 4 + 2]);
                    FMA2(v[c * 4 + 3], wd, rB.y, v[c * 4 + 3]);
                }
            }
            int n = 32;
            #pragma unroll
            for (int off = 16; off >= 1; off >>= 1) {
                n >>= 1;
                bool hi = (lane & off) != 0;
                #pragma unroll
                for (int i = 0; i < 16; i++) {
                    if (i < n) {
                        ull send = hi ? v[i] : v[i + n];
                        ull recv = __shfl_xor_sync(0xffffffffu, send, off);
                        ull keep = hi ? v[i + n] : v[i];
                        ADD2(v[i], keep, recv);
                    }
                }
            }
            partu[w * 32 + lane] = v[0];
        }
        __syncthreads();

        STAGE32(sw_u, g_owT + ((size_t)q << 13));
        CPA_COMMIT();
        if (tid < 256) {
            int t = tid >> 3, c = tid & 7;
            int tgg = t >> 3, rem = t & 7, j = rem >> 1, h = rem & 1;
            int item = c * 4 + j;
            float s = partf[((tgg * 4 + 0) * 32 + item) * 2 + h]
                    + partf[((tgg * 4 + 1) * 32 + item) * 2 + h]
                    + partf[((tgg * 4 + 2) * 32 + item) * 2 + h]
                    + partf[((tgg * 4 + 3) * 32 + item) * 2 + h]
                    + ib_s[q * CDIM + c]
                    - m_s[t] * vc_s[q * 8 + c];
            ze_s[t * 9 + c] = s;
        }
        __syncthreads();

        /* ====== phase 2 ====== */
        {
            int t = lane;
            ull ed[8];
            #pragma unroll
            for (int c = 0; c < 8; c++) {
                float e = ze_s[t * 9 + c];
                ed[c] = f2x(e, e);
            }
            const ull n2 = f2x(-2.0f, -2.0f);
            float best = 3.402823466e38f;
            int bk = 0;
            const int kb = w << 6;
            #pragma unroll 4
            for (int i = 0; i < 16; i++) {
                int k = kb + (i << 2);
                ull sA = 0ull, sB = 0ull;
                #pragma unroll
                for (int c = 0; c < 8; c++) {
                    ulonglong2 cv = *(const ulonglong2*)(cbt_s + c * 1024 + k);
                    FMA2(sA, cv.x, ed[c], sA);
                    FMA2(sB, cv.y, ed[c], sB);
                }
                ulonglong2 c2v = *(const ulonglong2*)(c2_s + k);
                ull bA, bB;
                FMA2(bA, sA, n2, c2v.x);
                FMA2(bB, sB, n2, c2v.y);
                float da, db, dc, dd;
                upk(bA, da, db); upk(bB, dc, dd);
                if (da < best) { best = da; bk = k;     }
                if (db < best) { best = db; bk = k + 1; }
                if (dc < best) { best = dc; bk = k + 2; }
                if (dd < best) { best = dd; bk = k + 3; }
            }
            bd_s[w * 32 + t] = best;
            bk_s[w * 32 + t] = bk;
        }
        __syncthreads();

        /* ---- select FIRST (smem gather from cbt_s) ---- */
        if (tid < TILE) {
            int t = tid;
            float best = bd_s[t];
            int bk = bk_s[t];
            #pragma unroll
            for (int kc = 1; kc < 16; kc++) {
                float d2 = bd_s[kc * 32 + t];
                if (d2 < best) { best = d2; bk = bk_s[kc * 32 + t]; }
            }
            if (widx) out[BDT + q * NCOLS + col0 + t] = (float)bk;
            float mt = m_s[t];
            float cw[8];
            #pragma unroll
            for (int c = 0; c < 8; c++) cw[c] = cbt_s[c * 1024 + bk];
            float* zp = zqp_f + (t >> 1) * 16 + (t & 1);
            #pragma unroll
            for (int c = 0; c < 8; c++) zp[c * 2] = -cw[c] * mt;
        }
        __syncthreads();                 /* cbt_s reads complete */

        if (q + 1 < NQ) {
            STAGE32(scbt_u, g_cbT + ((size_t)(q + 1) << 13));
            STAGE4(sc2_u,   g_c2 + ((size_t)(q + 1) << 10));
        }
        CPA_COMMIT();
        CPA_WAIT1();            /* ow[q] done; cbT[q+1] in flight */

        /* ====== phase 3 (packed, 4tg x 4dg) ====== */
        {
            ull zq0[8], zq1[8], zq2[8], zq3[8];
            #pragma unroll
            for (int c = 0; c < 8; c++) {
                zq0[c] = zqp_u[(tg * 4 + 0) * 8 + c];
                zq1[c] = zqp_u[(tg * 4 + 1) * 8 + c];
                zq2[c] = zqp_u[(tg * 4 + 2) * 8 + c];
                zq3[c] = zqp_u[(tg * 4 + 3) * 8 + c];
            }
            #pragma unroll 2
            for (int i = 0; i < 8; i++) {
                int d = dg * 256 + (i << 5) + lane;
                int sA = d * 8 + (tqa ^ (d & 7));
                int sB = d * 8 + (tqb ^ (d & 7));
                ulonglong2 ra = *(const ulonglong2*)&R4[sA];
                ulonglong2 rb = *(const ulonglong2*)&R4[sB];
                #pragma unroll
                for (int c = 0; c < 8; c++) {
                    float wv = w_s[c * 1024 + d];
                    ull wd = f2x(wv, wv);
                    FMA2(ra.x, wd, zq0[c], ra.x);
                    FMA2(ra.y, wd, zq1[c], ra.y);
                    FMA2(rb.x, wd, zq2[c], rb.x);
                    FMA2(rb.y, wd, zq3[c], rb.y);
                }
                *(ulonglong2*)&R4[sA] = ra;
                *(ulonglong2*)&R4[sB] = rb;
            }
        }
        __syncthreads();

        if (q + 1 < NQ) {
            STAGE32(sw_u, iw + ((size_t)(q + 1) << 13));
        }
        CPA_COMMIT();
    }

    if (wout) {
        #pragma unroll
        for (int it = 0; it < 16; it++) {
            int i = tid + it * NTH;
            int d = i >> 3, tq = i & 7;
            float4 zv = *(const float4*)(zb + (size_t)d * TDIM + (tq << 2));
            float4 rv = R4[d * 8 + (tq ^ (d & 7))];
            float obv = g_obsum[d];
            int tb = t0 + (tq << 2);
            float4 o;
            o.x = ((tb + 0 < len) ? zv.x + obv : 0.0f) - rv.x;
            o.y = ((tb + 1 < len) ? zv.y + obv : 0.0f) - rv.y;
            o.z = ((tb + 2 < len) ? zv.z + obv : 0.0f) - rv.z;
            o.w = ((tb + 3 < len) ? zv.w + obv : 0.0f) - rv.w;
            *(float4*)(out + (size_t)b * DDIM * TDIM + (size_t)d * TDIM + t0 + (tq << 2)) = o;
        }
    }
    if (wlen && blockIdx.x == 0 && tid < BDIMS)
        out[BDT + NQBT + tid] = (float)inlen[tid];
}

extern "C" void kernel_launch(void* const* d_in, const int* in_sizes, int n_in,
                              void* d_out, int out_size)
{
    const float* z   = (const float*)d_in[0];
    const float* iw  = (const float*)d_in[1];
    const float* ib  = (const float*)d_in[2];
    const float* ow  = (const float*)d_in[3];
    const float* ob  = (const float*)d_in[4];
    const float* cbk = (const float*)d_in[5];
    const int* inlen = (const int*)d_in[6];
    float* out = (float*)d_out;

    cudaFuncSetAttribute(rvq_kernel, cudaFuncAttributeMaxDynamicSharedMemorySize, SM_BYTES);

    int wout = (out_size >= BDT) ? 1 : 0;
    int widx = (out_size >= BDT + NQBT) ? 1 : 0;
    int wlen = (out_size >= BDT + NQBT + BDIMS) ? 1 : 0;

    prep0_kernel<<<4, 256>>>(ob);
    prep_kernel<<<256, 512>>>(ow, cbk);
    prepVc_kernel<<<NQ, 256>>>(iw);
    rvq_kernel<<<NCOLS / TILE, NTH, SM_BYTES>>>(z, iw, ib, cbk, inlen,
                                               out, wout, widx, wlen);
}